// round 2
// baseline (speedup 1.0000x reference)
#include <cuda_runtime.h>
#include <cstdint>

// ---------------------------------------------------------------------------
// Self-attention: x[8,2048,1024], kernel[3,1024,1024] -> out[8,2048,1024]
//   Q/K/V = x @ kernel[i]           (NN GEMM, M=16384, N=1024, K=1024)
//   S     = Q @ K^T * 1/8           (NT GEMM per batch, 2048x2048x1024)
//   A     = softmax(S, axis=-1)
//   out   = A @ V                   (NN GEMM per batch, 2048x1024x2048)
// Precision: 3xTF32 (hi/lo split) on Q-proj, K-proj, QK^T (softmax-sensitive);
// plain TF32 on V-proj and A@V.
// ---------------------------------------------------------------------------

static constexpr long long QKV_ONE = 16384LL * 1024LL;   // one of Q/K/V
__device__ float g_qkv[3 * 16384 * 1024];                // 201 MB scratch
__device__ float g_scores[8 * 2048 * 2048];              // 134 MB scratch

__device__ __forceinline__ uint32_t f2tf32(float x) {
    uint32_t r;
    asm("cvt.rna.tf32.f32 %0, %1;" : "=r"(r) : "f"(x));
    return r;
}

__device__ __forceinline__ void mma_tf32(float* d, const uint32_t* a, const uint32_t* b) {
    asm volatile(
        "mma.sync.aligned.m16n8k8.row.col.f32.tf32.tf32.f32 "
        "{%0,%1,%2,%3}, {%4,%5,%6,%7}, {%8,%9}, {%0,%1,%2,%3};"
        : "+f"(d[0]), "+f"(d[1]), "+f"(d[2]), "+f"(d[3])
        : "r"(a[0]), "r"(a[1]), "r"(a[2]), "r"(a[3]), "r"(b[0]), "r"(b[1]));
}

#define BM 128
#define BN 128
#define BKT 16
#define SSTR 20   // smem row stride (floats): conflict-free for frag loads

// BT: B is stored [N][K] (NT gemm, e.g. Q@K^T). else B is [K][N] (NN).
// THREE: 3xTF32 error-compensated path.
template <bool BT, bool THREE>
__global__ __launch_bounds__(256) void gemm_k(
    const float* __restrict__ Ag, const float* __restrict__ Bg, float* __restrict__ Cg,
    int K, int lda, int ldb, int ldc,
    long long batA, long long batB, long long batC)
{
    __shared__ uint32_t As_hi[BM][SSTR], Bs_hi[BN][SSTR];
    __shared__ uint32_t As_lo[BM][SSTR], Bs_lo[BN][SSTR];

    const int tid = threadIdx.x;
    const int lane = tid & 31;
    const int wid = tid >> 5;
    const int gid = lane >> 2;     // groupID (0..7)
    const int tig = lane & 3;      // threadID_in_group (0..3)
    const int wm = wid & 3;        // 4 warps along M (32 rows each)
    const int wn = wid >> 2;       // 2 warps along N (64 cols each)

    const long long rowBase = (long long)blockIdx.y * BM;
    const long long colBase = (long long)blockIdx.x * BN;
    const float* A = Ag + (long long)blockIdx.z * batA;
    const float* Bp = Bg + (long long)blockIdx.z * batB;
    float* C = Cg + (long long)blockIdx.z * batC;

    float d[2][8][4];
#pragma unroll
    for (int i = 0; i < 2; i++)
#pragma unroll
        for (int j = 0; j < 8; j++)
#pragma unroll
            for (int c = 0; c < 4; c++) d[i][j][c] = 0.f;

    for (int k0 = 0; k0 < K; k0 += BKT) {
        __syncthreads();
        // ---- fill A tile: 128 rows x 16 k, vectorized along k ----
#pragma unroll
        for (int p = 0; p < 2; p++) {
            int f = p * 256 + tid;           // float4 index 0..511
            int r = f >> 2, c = (f & 3) * 4; // r: row, c: k-col
            const float4 v = *(const float4*)(A + (rowBase + r) * (long long)lda + k0 + c);
            float vv[4] = {v.x, v.y, v.z, v.w};
#pragma unroll
            for (int j = 0; j < 4; j++) {
                uint32_t hi = f2tf32(vv[j]);
                As_hi[r][c + j] = hi;
                if (THREE) As_lo[r][c + j] = f2tf32(vv[j] - __uint_as_float(hi));
            }
        }
        // ---- fill B tile into Bs[n][k] ----
#pragma unroll
        for (int p = 0; p < 2; p++) {
            int f = p * 256 + tid;
            if (BT) {
                int r = f >> 2, c = (f & 3) * 4;  // r: n, c: k
                const float4 v = *(const float4*)(Bp + (colBase + r) * (long long)ldb + k0 + c);
                float vv[4] = {v.x, v.y, v.z, v.w};
#pragma unroll
                for (int j = 0; j < 4; j++) {
                    uint32_t hi = f2tf32(vv[j]);
                    Bs_hi[r][c + j] = hi;
                    if (THREE) Bs_lo[r][c + j] = f2tf32(vv[j] - __uint_as_float(hi));
                }
            } else {
                int kk = f >> 5, n4 = (f & 31) * 4;  // kk: k row, n4: n col
                const float4 v = *(const float4*)(Bp + (long long)(k0 + kk) * ldb + colBase + n4);
                float vv[4] = {v.x, v.y, v.z, v.w};
#pragma unroll
                for (int j = 0; j < 4; j++) {
                    uint32_t hi = f2tf32(vv[j]);
                    Bs_hi[n4 + j][kk] = hi;
                    if (THREE) Bs_lo[n4 + j][kk] = f2tf32(vv[j] - __uint_as_float(hi));
                }
            }
        }
        __syncthreads();

#pragma unroll
        for (int kk = 0; kk < BKT; kk += 8) {
            uint32_t a_hi[2][4], a_lo[2][4], b_hi[8][2], b_lo[8][2];
#pragma unroll
            for (int mt = 0; mt < 2; mt++) {
                int r0 = wm * 32 + mt * 16;
                a_hi[mt][0] = As_hi[r0 + gid][kk + tig];
                a_hi[mt][1] = As_hi[r0 + gid + 8][kk + tig];
                a_hi[mt][2] = As_hi[r0 + gid][kk + tig + 4];
                a_hi[mt][3] = As_hi[r0 + gid + 8][kk + tig + 4];
                if (THREE) {
                    a_lo[mt][0] = As_lo[r0 + gid][kk + tig];
                    a_lo[mt][1] = As_lo[r0 + gid + 8][kk + tig];
                    a_lo[mt][2] = As_lo[r0 + gid][kk + tig + 4];
                    a_lo[mt][3] = As_lo[r0 + gid + 8][kk + tig + 4];
                }
            }
#pragma unroll
            for (int nt = 0; nt < 8; nt++) {
                int n0 = wn * 64 + nt * 8;
                b_hi[nt][0] = Bs_hi[n0 + gid][kk + tig];
                b_hi[nt][1] = Bs_hi[n0 + gid][kk + tig + 4];
                if (THREE) {
                    b_lo[nt][0] = Bs_lo[n0 + gid][kk + tig];
                    b_lo[nt][1] = Bs_lo[n0 + gid][kk + tig + 4];
                }
            }
#pragma unroll
            for (int mt = 0; mt < 2; mt++)
#pragma unroll
                for (int nt = 0; nt < 8; nt++) {
                    mma_tf32(d[mt][nt], a_hi[mt], b_hi[nt]);
                    if (THREE) {
                        mma_tf32(d[mt][nt], a_hi[mt], b_lo[nt]);
                        mma_tf32(d[mt][nt], a_lo[mt], b_hi[nt]);
                    }
                }
        }
    }

    // ---- epilogue ----
#pragma unroll
    for (int mt = 0; mt < 2; mt++) {
        long long r0 = rowBase + wm * 32 + mt * 16 + gid;
#pragma unroll
        for (int nt = 0; nt < 8; nt++) {
            long long c0 = colBase + wn * 64 + nt * 8 + tig * 2;
            C[r0 * ldc + c0]           = d[mt][nt][0];
            C[r0 * ldc + c0 + 1]       = d[mt][nt][1];
            C[(r0 + 8) * ldc + c0]     = d[mt][nt][2];
            C[(r0 + 8) * ldc + c0 + 1] = d[mt][nt][3];
        }
    }
}

// one block (256 thr) per row of 2048; applies 1/sqrt(64) scale then softmax
__global__ __launch_bounds__(256) void softmax_k(float* __restrict__ sc) {
    const float SC = 0.125f;
    float* p = sc + (long long)blockIdx.x * 2048;
    const int t = threadIdx.x, lane = t & 31, w = t >> 5;

    float4 v0 = ((const float4*)p)[t];
    float4 v1 = ((const float4*)p)[t + 256];
    float x[8] = {v0.x, v0.y, v0.z, v0.w, v1.x, v1.y, v1.z, v1.w};

    float m = -1e30f;
#pragma unroll
    for (int i = 0; i < 8; i++) { x[i] *= SC; m = fmaxf(m, x[i]); }
#pragma unroll
    for (int o = 16; o > 0; o >>= 1) m = fmaxf(m, __shfl_xor_sync(0xffffffffu, m, o));

    __shared__ float red[8];
    if (lane == 0) red[w] = m;
    __syncthreads();
    float bm = red[0];
#pragma unroll
    for (int i = 1; i < 8; i++) bm = fmaxf(bm, red[i]);

    float s = 0.f;
#pragma unroll
    for (int i = 0; i < 8; i++) { x[i] = expf(x[i] - bm); s += x[i]; }
#pragma unroll
    for (int o = 16; o > 0; o >>= 1) s += __shfl_xor_sync(0xffffffffu, s, o);
    __syncthreads();               // everyone done reading red (max phase)
    if (lane == 0) red[w] = s;
    __syncthreads();
    float tot = 0.f;
#pragma unroll
    for (int i = 0; i < 8; i++) tot += red[i];
    float inv = 1.0f / tot;

    v0.x = x[0] * inv; v0.y = x[1] * inv; v0.z = x[2] * inv; v0.w = x[3] * inv;
    v1.x = x[4] * inv; v1.y = x[5] * inv; v1.z = x[6] * inv; v1.w = x[7] * inv;
    ((float4*)p)[t] = v0;
    ((float4*)p)[t + 256] = v1;
}

extern "C" void kernel_launch(void* const* d_in, const int* in_sizes, int n_in,
                              void* d_out, int out_size) {
    const float* x = (const float*)d_in[0];      // [8,2048,1024]
    const float* w = (const float*)d_in[1];      // [3,1024,1024]
    float* out = (float*)d_out;                  // [8,2048,1024]

    float* qkv = nullptr;
    float* scores = nullptr;
    cudaGetSymbolAddress((void**)&qkv, g_qkv);
    cudaGetSymbolAddress((void**)&scores, g_scores);

    dim3 blk(256);

    // Q, K projections (3xTF32): grid.z = 0,1 over kernel[0], kernel[1]
    gemm_k<false, true><<<dim3(8, 128, 2), blk>>>(
        x, w, qkv, 1024, 1024, 1024, 1024,
        0LL, 1024LL * 1024LL, QKV_ONE);

    // V projection (plain TF32)
    gemm_k<false, false><<<dim3(8, 128, 1), blk>>>(
        x, w + 2LL * 1024 * 1024, qkv + 2LL * QKV_ONE, 1024, 1024, 1024, 1024,
        0LL, 0LL, 0LL);

    // S = Q @ K^T per batch (3xTF32, NT)
    gemm_k<true, true><<<dim3(16, 16, 8), blk>>>(
        qkv, qkv + QKV_ONE, scores, 1024, 1024, 1024, 2048,
        2048LL * 1024LL, 2048LL * 1024LL, 2048LL * 2048LL);

    // softmax rows (scale folded in)
    softmax_k<<<16384, blk>>>(scores);

    // out = A @ V per batch (plain TF32, NN)
    gemm_k<false, false><<<dim3(8, 16, 8), blk>>>(
        scores, qkv + 2LL * QKV_ONE, out, 2048, 2048, 1024, 1024,
        2048LL * 2048LL, 2048LL * 1024LL, 2048LL * 1024LL);
}

// round 4
// speedup vs baseline: 2.2983x; 2.2983x over previous
#include <cuda_runtime.h>
#include <cuda_bf16.h>
#include <cstdint>

// ---------------------------------------------------------------------------
// Self-attention on sm_103 baseline ISA (no tcgen05 in this toolchain):
// mma.sync.m16n8k16 bf16 with 3xbf16 error compensation on every GEMM.
//   x[8,2048,1024] f32, kernel[3,1024,1024] f32 -> out[8,2048,1024] f32
// Every operand is an (hi, lo) bf16 pair; each GEMM computes
// Ahi*Bhi + Ahi*Blo + Alo*Bhi with fp32 accumulators (error ~2^-16).
// ---------------------------------------------------------------------------

#define BMT 128
#define BNT 128
#define BKT 32
#define PADS 40            // padded smem row stride (bf16 elems) -> 80 bytes
#define TILE_B (128 * PADS * 2)   // 10240 bytes per bf16 tile
#define STAGE_B (4 * TILE_B)      // Ahi, Alo, Bhi, Blo
#define SMEM_SZ (2 * STAGE_B)     // 81920 bytes

static constexpr long long QKV_ONE = 16384LL * 1024LL;

// scratch (device globals: allocation-guard safe)
__device__ __nv_bfloat16 g_xhi[16384LL * 1024], g_xlo[16384LL * 1024];
__device__ __nv_bfloat16 g_wthi[3LL * 1024 * 1024], g_wtlo[3LL * 1024 * 1024];
__device__ __nv_bfloat16 g_qkhi[2 * 16384LL * 1024], g_qklo[2 * 16384LL * 1024];
__device__ float         g_vf32[16384LL * 1024];
__device__ __nv_bfloat16 g_vthi[8LL * 1024 * 2048], g_vtlo[8LL * 1024 * 2048];
__device__ float         g_scores[8LL * 2048 * 2048];
__device__ __nv_bfloat16 g_shi[8LL * 2048 * 2048], g_slo[8LL * 2048 * 2048];

// ---------------- PTX helpers (all baseline sm_80-era) ----------------
__device__ __forceinline__ uint32_t s2u(const void* p) {
    uint32_t a;
    asm("{ .reg .u64 t; cvta.to.shared.u64 t, %1; cvt.u32.u64 %0, t; }" : "=r"(a) : "l"(p));
    return a;
}
__device__ __forceinline__ void cpasync16(uint32_t d, const void* s) {
    asm volatile("cp.async.cg.shared.global [%0], [%1], 16;" :: "r"(d), "l"(s) : "memory");
}
#define CP_COMMIT() asm volatile("cp.async.commit_group;" ::: "memory")
#define CP_WAIT(n)  asm volatile("cp.async.wait_group %0;" :: "n"(n) : "memory")

__device__ __forceinline__ void ldsm4(uint32_t* r, uint32_t a) {
    asm volatile("ldmatrix.sync.aligned.m8n8.x4.shared.b16 {%0,%1,%2,%3}, [%4];"
                 : "=r"(r[0]), "=r"(r[1]), "=r"(r[2]), "=r"(r[3]) : "r"(a));
}
__device__ __forceinline__ void mma_bf16(float* d, const uint32_t* a, const uint32_t* b) {
    asm volatile(
        "mma.sync.aligned.m16n8k16.row.col.f32.bf16.bf16.f32 "
        "{%0,%1,%2,%3}, {%4,%5,%6,%7}, {%8,%9}, {%0,%1,%2,%3};"
        : "+f"(d[0]), "+f"(d[1]), "+f"(d[2]), "+f"(d[3])
        : "r"(a[0]), "r"(a[1]), "r"(a[2]), "r"(a[3]), "r"(b[0]), "r"(b[1]));
}

// ---------------- 3xbf16 GEMM ----------------
// C[M,N] = sum_k A[m][k]*B[n][k]; A,B are K-major (hi,lo) bf16 pairs.
// SPLIT: emit (Chi, Clo) bf16 instead of fp32 C.
template <bool SPLIT>
__global__ __launch_bounds__(256) void bf3_gemm(
    const __nv_bfloat16* __restrict__ Ahi, const __nv_bfloat16* __restrict__ Alo,
    const __nv_bfloat16* __restrict__ Bhi, const __nv_bfloat16* __restrict__ Blo,
    float* __restrict__ C, __nv_bfloat16* __restrict__ Chi, __nv_bfloat16* __restrict__ Clo,
    int K, int lda, int ldb, int ldc,
    long long batA, long long batB, long long batC)
{
    extern __shared__ char smem[];
    const uint32_t sb = s2u(smem);
    const int tid = threadIdx.x;
    const int lane = tid & 31, warp = tid >> 5;
    const int wM = warp & 1;        // 2 warps along M (64 rows each)
    const int wN = warp >> 1;       // 4 warps along N (32 cols each)
    const int lm = lane >> 3, lr = lane & 7;
    const int gid = lane >> 2, tig = lane & 3;

    const long long rowBase = (long long)blockIdx.y * BMT;
    const long long colBase = (long long)blockIdx.x * BNT;
    const __nv_bfloat16* Ah = Ahi + blockIdx.z * batA;
    const __nv_bfloat16* Al = Alo + blockIdx.z * batA;
    const __nv_bfloat16* Bh = Bhi + blockIdx.z * batB;
    const __nv_bfloat16* Bl = Blo + blockIdx.z * batB;

    // per-lane ldmatrix offsets (bytes) within a 16x16 fragment window
    const uint32_t aOff = (uint32_t)(lr + (lm & 1) * 8) * (PADS * 2) + ((lm >> 1) * 8) * 2;
    const uint32_t bOff = (uint32_t)(lr + (lm >> 1) * 8) * (PADS * 2) + ((lm & 1) * 8) * 2;

    float acc[4][4][4];
#pragma unroll
    for (int i = 0; i < 4; i++)
#pragma unroll
        for (int j = 0; j < 4; j++)
#pragma unroll
            for (int c = 0; c < 4; c++) acc[i][j][c] = 0.f;

    const int nCh = K / BKT;

    auto loadStage = [&](int c) {
        const uint32_t st = sb + (uint32_t)(c & 1) * STAGE_B;
        const long long k0 = (long long)c * BKT;
        const int r = tid >> 2, cc = tid & 3;           // 64 rows x 4 chunks per pass
#pragma unroll
        for (int h = 0; h < 2; h++) {
            const __nv_bfloat16* ga = h ? Al : Ah;
            const uint32_t ta = st + h * TILE_B;
#pragma unroll
            for (int i = 0; i < 2; i++) {               // rows r and r+64
                int rr = r + i * 64;
                cpasync16(ta + rr * (PADS * 2) + cc * 16,
                          (const char*)(ga + (rowBase + rr) * (long long)lda + k0) + cc * 16);
            }
            const __nv_bfloat16* gb = h ? Bl : Bh;
            const uint32_t tb = st + (2 + h) * TILE_B;
#pragma unroll
            for (int i = 0; i < 2; i++) {
                int rr = r + i * 64;
                cpasync16(tb + rr * (PADS * 2) + cc * 16,
                          (const char*)(gb + (colBase + rr) * (long long)ldb + k0) + cc * 16);
            }
        }
        CP_COMMIT();
    };

    loadStage(0);

    for (int c = 0; c < nCh; ++c) {
        if (c + 1 < nCh) { loadStage(c + 1); CP_WAIT(1); }
        else             { CP_WAIT(0); }
        __syncthreads();

        const uint32_t st = sb + (uint32_t)(c & 1) * STAGE_B;
        const uint32_t sAh = st, sAl = st + TILE_B, sBh = st + 2 * TILE_B, sBl = st + 3 * TILE_B;

#pragma unroll
        for (int ks = 0; ks < BKT; ks += 16) {
            uint32_t af[4][4], bf_[2][4];
            const uint32_t ak = aOff + ks * 2, bk = bOff + ks * 2;

            // phase 1: Ahi * Bhi
#pragma unroll
            for (int mt = 0; mt < 4; mt++)
                ldsm4(af[mt], sAh + (wM * 64 + mt * 16) * (PADS * 2) + ak);
#pragma unroll
            for (int p = 0; p < 2; p++)
                ldsm4(bf_[p], sBh + (wN * 32 + p * 16) * (PADS * 2) + bk);
#pragma unroll
            for (int mt = 0; mt < 4; mt++)
#pragma unroll
                for (int nt = 0; nt < 4; nt++)
                    mma_bf16(acc[mt][nt], af[mt], &bf_[nt >> 1][(nt & 1) * 2]);

            // phase 2: Ahi * Blo
#pragma unroll
            for (int p = 0; p < 2; p++)
                ldsm4(bf_[p], sBl + (wN * 32 + p * 16) * (PADS * 2) + bk);
#pragma unroll
            for (int mt = 0; mt < 4; mt++)
#pragma unroll
                for (int nt = 0; nt < 4; nt++)
                    mma_bf16(acc[mt][nt], af[mt], &bf_[nt >> 1][(nt & 1) * 2]);

            // phase 3: Alo * Bhi
#pragma unroll
            for (int mt = 0; mt < 4; mt++)
                ldsm4(af[mt], sAl + (wM * 64 + mt * 16) * (PADS * 2) + ak);
#pragma unroll
            for (int p = 0; p < 2; p++)
                ldsm4(bf_[p], sBh + (wN * 32 + p * 16) * (PADS * 2) + bk);
#pragma unroll
            for (int mt = 0; mt < 4; mt++)
#pragma unroll
                for (int nt = 0; nt < 4; nt++)
                    mma_bf16(acc[mt][nt], af[mt], &bf_[nt >> 1][(nt & 1) * 2]);
        }
        __syncthreads();
    }

    // ---- epilogue ----
#pragma unroll
    for (int mt = 0; mt < 4; mt++) {
        const long long r0 = rowBase + wM * 64 + mt * 16 + gid;
#pragma unroll
        for (int nt = 0; nt < 4; nt++) {
            const long long c0 = colBase + wN * 32 + nt * 8 + tig * 2;
            if (SPLIT) {
                __nv_bfloat16* ch = Chi + blockIdx.z * batC;
                __nv_bfloat16* cl = Clo + blockIdx.z * batC;
#pragma unroll
                for (int half = 0; half < 2; half++) {
                    float v0 = acc[mt][nt][2 * half], v1 = acc[mt][nt][2 * half + 1];
                    __nv_bfloat16 h0 = __float2bfloat16(v0);
                    __nv_bfloat16 h1 = __float2bfloat16(v1);
                    __nv_bfloat16 l0 = __float2bfloat16(v0 - __bfloat162float(h0));
                    __nv_bfloat16 l1 = __float2bfloat16(v1 - __bfloat162float(h1));
                    long long idx = (r0 + half * 8) * ldc + c0;
                    *(__nv_bfloat162*)&ch[idx] = __nv_bfloat162(h0, h1);
                    *(__nv_bfloat162*)&cl[idx] = __nv_bfloat162(l0, l1);
                }
            } else {
                float* cp = C + blockIdx.z * batC;
                *(float2*)&cp[r0 * ldc + c0] =
                    make_float2(acc[mt][nt][0], acc[mt][nt][1]);
                *(float2*)&cp[(r0 + 8) * ldc + c0] =
                    make_float2(acc[mt][nt][2], acc[mt][nt][3]);
            }
        }
    }
}

// ---------------- conversion kernels ----------------
__global__ __launch_bounds__(256) void split_x(
    const float4* __restrict__ in, __nv_bfloat16* __restrict__ hi,
    __nv_bfloat16* __restrict__ lo, int n4)
{
    int i = blockIdx.x * 256 + threadIdx.x;
    if (i >= n4) return;
    float4 v = in[i];
    float vv[4] = {v.x, v.y, v.z, v.w};
    __nv_bfloat16 h[4], l[4];
#pragma unroll
    for (int j = 0; j < 4; j++) {
        h[j] = __float2bfloat16(vv[j]);
        l[j] = __float2bfloat16(vv[j] - __bfloat162float(h[j]));
    }
    ((__nv_bfloat162*)hi)[2 * i]     = __nv_bfloat162(h[0], h[1]);
    ((__nv_bfloat162*)hi)[2 * i + 1] = __nv_bfloat162(h[2], h[3]);
    ((__nv_bfloat162*)lo)[2 * i]     = __nv_bfloat162(l[0], l[1]);
    ((__nv_bfloat162*)lo)[2 * i + 1] = __nv_bfloat162(l[2], l[3]);
}

// out[c][r] = in[r][c], split hi/lo. block 32x8
__global__ __launch_bounds__(256) void transpose_split(
    const float* __restrict__ in, __nv_bfloat16* __restrict__ hi,
    __nv_bfloat16* __restrict__ lo, int R, int C, long long batIn, long long batOut)
{
    __shared__ float t[32][33];
    const float* ip = in + blockIdx.z * batIn;
    const long long ob = blockIdx.z * batOut;
    const int c0 = blockIdx.x * 32, r0 = blockIdx.y * 32;
    const int tx = threadIdx.x, ty = threadIdx.y;
#pragma unroll
    for (int i = 0; i < 32; i += 8)
        t[ty + i][tx] = ip[(long long)(r0 + ty + i) * C + c0 + tx];
    __syncthreads();
#pragma unroll
    for (int i = 0; i < 32; i += 8) {
        float v = t[tx][ty + i];
        __nv_bfloat16 h = __float2bfloat16(v);
        __nv_bfloat16 l = __float2bfloat16(v - __bfloat162float(h));
        long long idx = ob + (long long)(c0 + ty + i) * R + r0 + tx;
        hi[idx] = h;
        lo[idx] = l;
    }
}

// softmax over rows of 2048; scale 1/8 folded in; writes hi/lo bf16
__global__ __launch_bounds__(256) void softmax_split(
    const float* __restrict__ sc, __nv_bfloat16* __restrict__ hi,
    __nv_bfloat16* __restrict__ lo)
{
    const float SC = 0.125f;
    const long long row = blockIdx.x;
    const float* p = sc + row * 2048;
    const int t = threadIdx.x, lane = t & 31, w = t >> 5;

    float4 v0 = ((const float4*)p)[t];
    float4 v1 = ((const float4*)p)[t + 256];
    float x[8] = {v0.x, v0.y, v0.z, v0.w, v1.x, v1.y, v1.z, v1.w};

    float m = -1e30f;
#pragma unroll
    for (int i = 0; i < 8; i++) { x[i] *= SC; m = fmaxf(m, x[i]); }
#pragma unroll
    for (int o = 16; o > 0; o >>= 1) m = fmaxf(m, __shfl_xor_sync(0xffffffffu, m, o));

    __shared__ float red[8];
    if (lane == 0) red[w] = m;
    __syncthreads();
    float bm = red[0];
#pragma unroll
    for (int i = 1; i < 8; i++) bm = fmaxf(bm, red[i]);

    float s = 0.f;
#pragma unroll
    for (int i = 0; i < 8; i++) { x[i] = expf(x[i] - bm); s += x[i]; }
#pragma unroll
    for (int o = 16; o > 0; o >>= 1) s += __shfl_xor_sync(0xffffffffu, s, o);
    __syncthreads();
    if (lane == 0) red[w] = s;
    __syncthreads();
    float tot = 0.f;
#pragma unroll
    for (int i = 0; i < 8; i++) tot += red[i];
    const float inv = 1.0f / tot;

    __nv_bfloat162* hp0 = (__nv_bfloat162*)(hi + row * 2048) + 2 * t;
    __nv_bfloat162* lp0 = (__nv_bfloat162*)(lo + row * 2048) + 2 * t;
    __nv_bfloat162* hp1 = hp0 + 512;
    __nv_bfloat162* lp1 = lp0 + 512;
    __nv_bfloat16 h[8], l[8];
#pragma unroll
    for (int i = 0; i < 8; i++) {
        float y = x[i] * inv;
        h[i] = __float2bfloat16(y);
        l[i] = __float2bfloat16(y - __bfloat162float(h[i]));
    }
    hp0[0] = __nv_bfloat162(h[0], h[1]); hp0[1] = __nv_bfloat162(h[2], h[3]);
    hp1[0] = __nv_bfloat162(h[4], h[5]); hp1[1] = __nv_bfloat162(h[6], h[7]);
    lp0[0] = __nv_bfloat162(l[0], l[1]); lp0[1] = __nv_bfloat162(l[2], l[3]);
    lp1[0] = __nv_bfloat162(l[4], l[5]); lp1[1] = __nv_bfloat162(l[6], l[7]);
}

// ---------------- host ----------------
extern "C" void kernel_launch(void* const* d_in, const int* in_sizes, int n_in,
                              void* d_out, int out_size) {
    const float* x = (const float*)d_in[0];
    const float* w = (const float*)d_in[1];
    float* out = (float*)d_out;

    __nv_bfloat16 *xhi, *xlo, *wthi, *wtlo, *qkhi, *qklo, *vthi, *vtlo, *shi, *slo;
    float *vf32, *scores;
    cudaGetSymbolAddress((void**)&xhi, g_xhi);
    cudaGetSymbolAddress((void**)&xlo, g_xlo);
    cudaGetSymbolAddress((void**)&wthi, g_wthi);
    cudaGetSymbolAddress((void**)&wtlo, g_wtlo);
    cudaGetSymbolAddress((void**)&qkhi, g_qkhi);
    cudaGetSymbolAddress((void**)&qklo, g_qklo);
    cudaGetSymbolAddress((void**)&vf32, g_vf32);
    cudaGetSymbolAddress((void**)&vthi, g_vthi);
    cudaGetSymbolAddress((void**)&vtlo, g_vtlo);
    cudaGetSymbolAddress((void**)&scores, g_scores);
    cudaGetSymbolAddress((void**)&shi, g_shi);
    cudaGetSymbolAddress((void**)&slo, g_slo);

    cudaFuncSetAttribute(bf3_gemm<true>,  cudaFuncAttributeMaxDynamicSharedMemorySize, SMEM_SZ);
    cudaFuncSetAttribute(bf3_gemm<false>, cudaFuncAttributeMaxDynamicSharedMemorySize, SMEM_SZ);

    // 1) split x -> hi/lo bf16
    split_x<<<16384, 256>>>((const float4*)x, xhi, xlo, 16384 * 1024 / 4);

    // 2) transpose+split W -> wt[z][d][h]
    transpose_split<<<dim3(32, 32, 3), dim3(32, 8)>>>(
        w, wthi, wtlo, 1024, 1024, 1024LL * 1024, 1024LL * 1024);

    // 3) Q,K projections -> split bf16 output (M=16384,N=1024,K=1024)
    bf3_gemm<true><<<dim3(8, 128, 2), 256, SMEM_SZ>>>(
        xhi, xlo, wthi, wtlo, nullptr, qkhi, qklo,
        1024, 1024, 1024, 1024, 0LL, 1024LL * 1024, QKV_ONE);

    // 4) V projection -> fp32
    bf3_gemm<false><<<dim3(8, 128, 1), 256, SMEM_SZ>>>(
        xhi, xlo, wthi + 2LL * 1024 * 1024, wtlo + 2LL * 1024 * 1024,
        vf32, nullptr, nullptr,
        1024, 1024, 1024, 1024, 0LL, 0LL, 0LL);

    // 5) transpose+split V per batch -> vt[b][d][s]
    transpose_split<<<dim3(32, 64, 8), dim3(32, 8)>>>(
        vf32, vthi, vtlo, 2048, 1024, 2048LL * 1024, 1024LL * 2048);

    // 6) S = Q @ K^T per batch (M=2048,N=2048,K=1024) -> fp32 scores
    bf3_gemm<false><<<dim3(16, 16, 8), 256, SMEM_SZ>>>(
        qkhi, qklo, qkhi + QKV_ONE, qklo + QKV_ONE, scores, nullptr, nullptr,
        1024, 1024, 1024, 2048, 2048LL * 1024, 2048LL * 1024, 2048LL * 2048);

    // 7) softmax (+split to bf16 hi/lo)
    softmax_split<<<16384, 256>>>(scores, shi, slo);

    // 8) out = A @ V per batch (M=2048,N=1024,K=2048)
    bf3_gemm<false><<<dim3(8, 16, 8), 256, SMEM_SZ>>>(
        shi, slo, vthi, vtlo, out, nullptr, nullptr,
        2048, 2048, 2048, 1024, 2048LL * 2048, 1024LL * 2048, 2048LL * 1024);
}

// round 5
// speedup vs baseline: 2.7737x; 1.2068x over previous
#include <cuda_runtime.h>
#include <cuda_bf16.h>
#include <cstdint>

// ---------------------------------------------------------------------------
// Self-attention, sm_103 baseline ISA: mma.sync m16n8k16 bf16, 3xbf16
// error compensation (Ahi*Bhi + Ahi*Blo + Alo*Bhi) on every GEMM.
// Round 5: 2 CTAs/SM (launch_bounds 256,2) + B-resident phase order.
// ---------------------------------------------------------------------------

#define BMT 128
#define BNT 128
#define BKT 32
#define PADS 40            // padded smem row stride (bf16 elems) -> 80 bytes
#define TILE_B (128 * PADS * 2)   // 10240 bytes per bf16 tile
#define STAGE_B (4 * TILE_B)      // Ahi, Alo, Bhi, Blo
#define SMEM_SZ (2 * STAGE_B)     // 81920 bytes

static constexpr long long QKV_ONE = 16384LL * 1024LL;

__device__ __nv_bfloat16 g_xhi[16384LL * 1024], g_xlo[16384LL * 1024];
__device__ __nv_bfloat16 g_wthi[3LL * 1024 * 1024], g_wtlo[3LL * 1024 * 1024];
__device__ __nv_bfloat16 g_qkhi[2 * 16384LL * 1024], g_qklo[2 * 16384LL * 1024];
__device__ float         g_vf32[16384LL * 1024];
__device__ __nv_bfloat16 g_vthi[8LL * 1024 * 2048], g_vtlo[8LL * 1024 * 2048];
__device__ float         g_scores[8LL * 2048 * 2048];
__device__ __nv_bfloat16 g_shi[8LL * 2048 * 2048], g_slo[8LL * 2048 * 2048];

// ---------------- PTX helpers ----------------
__device__ __forceinline__ uint32_t s2u(const void* p) {
    uint32_t a;
    asm("{ .reg .u64 t; cvta.to.shared.u64 t, %1; cvt.u32.u64 %0, t; }" : "=r"(a) : "l"(p));
    return a;
}
__device__ __forceinline__ void cpasync16(uint32_t d, const void* s) {
    asm volatile("cp.async.cg.shared.global [%0], [%1], 16;" :: "r"(d), "l"(s) : "memory");
}
#define CP_COMMIT() asm volatile("cp.async.commit_group;" ::: "memory")
#define CP_WAIT(n)  asm volatile("cp.async.wait_group %0;" :: "n"(n) : "memory")

__device__ __forceinline__ void ldsm4(uint32_t* r, uint32_t a) {
    asm volatile("ldmatrix.sync.aligned.m8n8.x4.shared.b16 {%0,%1,%2,%3}, [%4];"
                 : "=r"(r[0]), "=r"(r[1]), "=r"(r[2]), "=r"(r[3]) : "r"(a));
}
__device__ __forceinline__ void mma_bf16(float* d, const uint32_t* a, const uint32_t* b) {
    asm volatile(
        "mma.sync.aligned.m16n8k16.row.col.f32.bf16.bf16.f32 "
        "{%0,%1,%2,%3}, {%4,%5,%6,%7}, {%8,%9}, {%0,%1,%2,%3};"
        : "+f"(d[0]), "+f"(d[1]), "+f"(d[2]), "+f"(d[3])
        : "r"(a[0]), "r"(a[1]), "r"(a[2]), "r"(a[3]), "r"(b[0]), "r"(b[1]));
}

// ---------------- 3xbf16 GEMM ----------------
template <bool SPLIT>
__global__ __launch_bounds__(256, 2) void bf3_gemm(
    const __nv_bfloat16* __restrict__ Ahi, const __nv_bfloat16* __restrict__ Alo,
    const __nv_bfloat16* __restrict__ Bhi, const __nv_bfloat16* __restrict__ Blo,
    float* __restrict__ C, __nv_bfloat16* __restrict__ Chi, __nv_bfloat16* __restrict__ Clo,
    int K, int lda, int ldb, int ldc,
    long long batA, long long batB, long long batC)
{
    extern __shared__ char smem[];
    const uint32_t sb = s2u(smem);
    const int tid = threadIdx.x;
    const int lane = tid & 31, warp = tid >> 5;
    const int wM = warp & 1;        // 2 warps along M (64 rows)
    const int wN = warp >> 1;       // 4 warps along N (32 cols)
    const int lm = lane >> 3, lr = lane & 7;
    const int gid = lane >> 2, tig = lane & 3;

    const long long rowBase = (long long)blockIdx.y * BMT;
    const long long colBase = (long long)blockIdx.x * BNT;
    const __nv_bfloat16* Ah = Ahi + blockIdx.z * batA;
    const __nv_bfloat16* Al = Alo + blockIdx.z * batA;
    const __nv_bfloat16* Bh = Bhi + blockIdx.z * batB;
    const __nv_bfloat16* Bl = Blo + blockIdx.z * batB;

    const uint32_t aOff = (uint32_t)(lr + (lm & 1) * 8) * (PADS * 2) + ((lm >> 1) * 8) * 2;
    const uint32_t bOff = (uint32_t)(lr + (lm >> 1) * 8) * (PADS * 2) + ((lm & 1) * 8) * 2;

    float acc[4][4][4];
#pragma unroll
    for (int i = 0; i < 4; i++)
#pragma unroll
        for (int j = 0; j < 4; j++)
#pragma unroll
            for (int c = 0; c < 4; c++) acc[i][j][c] = 0.f;

    const int nCh = K / BKT;

    auto loadStage = [&](int c) {
        const uint32_t st = sb + (uint32_t)(c & 1) * STAGE_B;
        const long long k0 = (long long)c * BKT;
        const int r = tid >> 2, cc = tid & 3;
#pragma unroll
        for (int h = 0; h < 2; h++) {
            const __nv_bfloat16* ga = h ? Al : Ah;
            const uint32_t ta = st + h * TILE_B;
#pragma unroll
            for (int i = 0; i < 2; i++) {
                int rr = r + i * 64;
                cpasync16(ta + rr * (PADS * 2) + cc * 16,
                          (const char*)(ga + (rowBase + rr) * (long long)lda + k0) + cc * 16);
            }
            const __nv_bfloat16* gb = h ? Bl : Bh;
            const uint32_t tb = st + (2 + h) * TILE_B;
#pragma unroll
            for (int i = 0; i < 2; i++) {
                int rr = r + i * 64;
                cpasync16(tb + rr * (PADS * 2) + cc * 16,
                          (const char*)(gb + (colBase + rr) * (long long)ldb + k0) + cc * 16);
            }
        }
        CP_COMMIT();
    };

    loadStage(0);

    for (int c = 0; c < nCh; ++c) {
        if (c + 1 < nCh) { loadStage(c + 1); CP_WAIT(1); }
        else             { CP_WAIT(0); }
        __syncthreads();

        const uint32_t st = sb + (uint32_t)(c & 1) * STAGE_B;
        const uint32_t sAh = st, sAl = st + TILE_B, sBh = st + 2 * TILE_B, sBl = st + 3 * TILE_B;

#pragma unroll
        for (int ks = 0; ks < BKT; ks += 16) {
            uint32_t af[4][4], bh_[2][4], bl_[2][4];
            const uint32_t ak = aOff + ks * 2, bk = bOff + ks * 2;

            // load Ahi, Bhi, Blo up front (B stays resident all 3 phases)
#pragma unroll
            for (int mt = 0; mt < 4; mt++)
                ldsm4(af[mt], sAh + (wM * 64 + mt * 16) * (PADS * 2) + ak);
#pragma unroll
            for (int p = 0; p < 2; p++) {
                ldsm4(bh_[p], sBh + (wN * 32 + p * 16) * (PADS * 2) + bk);
                ldsm4(bl_[p], sBl + (wN * 32 + p * 16) * (PADS * 2) + bk);
            }

            // phase 1: Ahi * Bhi
#pragma unroll
            for (int mt = 0; mt < 4; mt++)
#pragma unroll
                for (int nt = 0; nt < 4; nt++)
                    mma_bf16(acc[mt][nt], af[mt], &bh_[nt >> 1][(nt & 1) * 2]);

            // phase 2: Ahi * Blo (no loads between phases 1-2)
#pragma unroll
            for (int mt = 0; mt < 4; mt++)
#pragma unroll
                for (int nt = 0; nt < 4; nt++)
                    mma_bf16(acc[mt][nt], af[mt], &bl_[nt >> 1][(nt & 1) * 2]);

            // phase 3: Alo * Bhi (reload A only)
#pragma unroll
            for (int mt = 0; mt < 4; mt++)
                ldsm4(af[mt], sAl + (wM * 64 + mt * 16) * (PADS * 2) + ak);
#pragma unroll
            for (int mt = 0; mt < 4; mt++)
#pragma unroll
                for (int nt = 0; nt < 4; nt++)
                    mma_bf16(acc[mt][nt], af[mt], &bh_[nt >> 1][(nt & 1) * 2]);
        }
        __syncthreads();
    }

    // ---- epilogue ----
#pragma unroll
    for (int mt = 0; mt < 4; mt++) {
        const long long r0 = rowBase + wM * 64 + mt * 16 + gid;
#pragma unroll
        for (int nt = 0; nt < 4; nt++) {
            const long long c0 = colBase + wN * 32 + nt * 8 + tig * 2;
            if (SPLIT) {
                __nv_bfloat16* ch = Chi + blockIdx.z * batC;
                __nv_bfloat16* cl = Clo + blockIdx.z * batC;
#pragma unroll
                for (int half = 0; half < 2; half++) {
                    float v0 = acc[mt][nt][2 * half], v1 = acc[mt][nt][2 * half + 1];
                    __nv_bfloat16 h0 = __float2bfloat16(v0);
                    __nv_bfloat16 h1 = __float2bfloat16(v1);
                    __nv_bfloat16 l0 = __float2bfloat16(v0 - __bfloat162float(h0));
                    __nv_bfloat16 l1 = __float2bfloat16(v1 - __bfloat162float(h1));
                    long long idx = (r0 + half * 8) * ldc + c0;
                    *(__nv_bfloat162*)&ch[idx] = __nv_bfloat162(h0, h1);
                    *(__nv_bfloat162*)&cl[idx] = __nv_bfloat162(l0, l1);
                }
            } else {
                float* cp = C + blockIdx.z * batC;
                *(float2*)&cp[r0 * ldc + c0] =
                    make_float2(acc[mt][nt][0], acc[mt][nt][1]);
                *(float2*)&cp[(r0 + 8) * ldc + c0] =
                    make_float2(acc[mt][nt][2], acc[mt][nt][3]);
            }
        }
    }
}

// ---------------- conversion kernels ----------------
__global__ __launch_bounds__(256) void split_x(
    const float4* __restrict__ in, __nv_bfloat16* __restrict__ hi,
    __nv_bfloat16* __restrict__ lo, int n4)
{
    int i = blockIdx.x * 256 + threadIdx.x;
    if (i >= n4) return;
    float4 v = in[i];
    float vv[4] = {v.x, v.y, v.z, v.w};
    __nv_bfloat16 h[4], l[4];
#pragma unroll
    for (int j = 0; j < 4; j++) {
        h[j] = __float2bfloat16(vv[j]);
        l[j] = __float2bfloat16(vv[j] - __bfloat162float(h[j]));
    }
    ((__nv_bfloat162*)hi)[2 * i]     = __nv_bfloat162(h[0], h[1]);
    ((__nv_bfloat162*)hi)[2 * i + 1] = __nv_bfloat162(h[2], h[3]);
    ((__nv_bfloat162*)lo)[2 * i]     = __nv_bfloat162(l[0], l[1]);
    ((__nv_bfloat162*)lo)[2 * i + 1] = __nv_bfloat162(l[2], l[3]);
}

__global__ __launch_bounds__(256) void transpose_split(
    const float* __restrict__ in, __nv_bfloat16* __restrict__ hi,
    __nv_bfloat16* __restrict__ lo, int R, int C, long long batIn, long long batOut)
{
    __shared__ float t[32][33];
    const float* ip = in + blockIdx.z * batIn;
    const long long ob = blockIdx.z * batOut;
    const int c0 = blockIdx.x * 32, r0 = blockIdx.y * 32;
    const int tx = threadIdx.x, ty = threadIdx.y;
#pragma unroll
    for (int i = 0; i < 32; i += 8)
        t[ty + i][tx] = ip[(long long)(r0 + ty + i) * C + c0 + tx];
    __syncthreads();
#pragma unroll
    for (int i = 0; i < 32; i += 8) {
        float v = t[tx][ty + i];
        __nv_bfloat16 h = __float2bfloat16(v);
        __nv_bfloat16 l = __float2bfloat16(v - __bfloat162float(h));
        long long idx = ob + (long long)(c0 + ty + i) * R + r0 + tx;
        hi[idx] = h;
        lo[idx] = l;
    }
}

__global__ __launch_bounds__(256) void softmax_split(
    const float* __restrict__ sc, __nv_bfloat16* __restrict__ hi,
    __nv_bfloat16* __restrict__ lo)
{
    const float SC = 0.125f;
    const long long row = blockIdx.x;
    const float* p = sc + row * 2048;
    const int t = threadIdx.x, lane = t & 31, w = t >> 5;

    float4 v0 = ((const float4*)p)[t];
    float4 v1 = ((const float4*)p)[t + 256];
    float x[8] = {v0.x, v0.y, v0.z, v0.w, v1.x, v1.y, v1.z, v1.w};

    float m = -1e30f;
#pragma unroll
    for (int i = 0; i < 8; i++) { x[i] *= SC; m = fmaxf(m, x[i]); }
#pragma unroll
    for (int o = 16; o > 0; o >>= 1) m = fmaxf(m, __shfl_xor_sync(0xffffffffu, m, o));

    __shared__ float red[8];
    if (lane == 0) red[w] = m;
    __syncthreads();
    float bm = red[0];
#pragma unroll
    for (int i = 1; i < 8; i++) bm = fmaxf(bm, red[i]);

    float s = 0.f;
#pragma unroll
    for (int i = 0; i < 8; i++) { x[i] = expf(x[i] - bm); s += x[i]; }
#pragma unroll
    for (int o = 16; o > 0; o >>= 1) s += __shfl_xor_sync(0xffffffffu, s, o);
    __syncthreads();
    if (lane == 0) red[w] = s;
    __syncthreads();
    float tot = 0.f;
#pragma unroll
    for (int i = 0; i < 8; i++) tot += red[i];
    const float inv = 1.0f / tot;

    __nv_bfloat162* hp0 = (__nv_bfloat162*)(hi + row * 2048) + 2 * t;
    __nv_bfloat162* lp0 = (__nv_bfloat162*)(lo + row * 2048) + 2 * t;
    __nv_bfloat162* hp1 = hp0 + 512;
    __nv_bfloat162* lp1 = lp0 + 512;
    __nv_bfloat16 h[8], l[8];
#pragma unroll
    for (int i = 0; i < 8; i++) {
        float y = x[i] * inv;
        h[i] = __float2bfloat16(y);
        l[i] = __float2bfloat16(y - __bfloat162float(h[i]));
    }
    hp0[0] = __nv_bfloat162(h[0], h[1]); hp0[1] = __nv_bfloat162(h[2], h[3]);
    hp1[0] = __nv_bfloat162(h[4], h[5]); hp1[1] = __nv_bfloat162(h[6], h[7]);
    lp0[0] = __nv_bfloat162(l[0], l[1]); lp0[1] = __nv_bfloat162(l[2], l[3]);
    lp1[0] = __nv_bfloat162(l[4], l[5]); lp1[1] = __nv_bfloat162(l[6], l[7]);
}

// ---------------- host ----------------
extern "C" void kernel_launch(void* const* d_in, const int* in_sizes, int n_in,
                              void* d_out, int out_size) {
    const float* x = (const float*)d_in[0];
    const float* w = (const float*)d_in[1];
    float* out = (float*)d_out;

    __nv_bfloat16 *xhi, *xlo, *wthi, *wtlo, *qkhi, *qklo, *vthi, *vtlo, *shi, *slo;
    float *vf32, *scores;
    cudaGetSymbolAddress((void**)&xhi, g_xhi);
    cudaGetSymbolAddress((void**)&xlo, g_xlo);
    cudaGetSymbolAddress((void**)&wthi, g_wthi);
    cudaGetSymbolAddress((void**)&wtlo, g_wtlo);
    cudaGetSymbolAddress((void**)&qkhi, g_qkhi);
    cudaGetSymbolAddress((void**)&qklo, g_qklo);
    cudaGetSymbolAddress((void**)&vf32, g_vf32);
    cudaGetSymbolAddress((void**)&vthi, g_vthi);
    cudaGetSymbolAddress((void**)&vtlo, g_vtlo);
    cudaGetSymbolAddress((void**)&scores, g_scores);
    cudaGetSymbolAddress((void**)&shi, g_shi);
    cudaGetSymbolAddress((void**)&slo, g_slo);

    cudaFuncSetAttribute(bf3_gemm<true>,  cudaFuncAttributeMaxDynamicSharedMemorySize, SMEM_SZ);
    cudaFuncSetAttribute(bf3_gemm<false>, cudaFuncAttributeMaxDynamicSharedMemorySize, SMEM_SZ);

    split_x<<<16384, 256>>>((const float4*)x, xhi, xlo, 16384 * 1024 / 4);

    transpose_split<<<dim3(32, 32, 3), dim3(32, 8)>>>(
        w, wthi, wtlo, 1024, 1024, 1024LL * 1024, 1024LL * 1024);

    bf3_gemm<true><<<dim3(8, 128, 2), 256, SMEM_SZ>>>(
        xhi, xlo, wthi, wtlo, nullptr, qkhi, qklo,
        1024, 1024, 1024, 1024, 0LL, 1024LL * 1024, QKV_ONE);

    bf3_gemm<false><<<dim3(8, 128, 1), 256, SMEM_SZ>>>(
        xhi, xlo, wthi + 2LL * 1024 * 1024, wtlo + 2LL * 1024 * 1024,
        vf32, nullptr, nullptr,
        1024, 1024, 1024, 1024, 0LL, 0LL, 0LL);

    transpose_split<<<dim3(32, 64, 8), dim3(32, 8)>>>(
        vf32, vthi, vtlo, 2048, 1024, 2048LL * 1024, 1024LL * 2048);

    bf3_gemm<false><<<dim3(16, 16, 8), 256, SMEM_SZ>>>(
        qkhi, qklo, qkhi + QKV_ONE, qklo + QKV_ONE, scores, nullptr, nullptr,
        1024, 1024, 1024, 2048, 2048LL * 1024, 2048LL * 1024, 2048LL * 2048);

    softmax_split<<<16384, 256>>>(scores, shi, slo);

    bf3_gemm<false><<<dim3(8, 16, 8), 256, SMEM_SZ>>>(
        shi, slo, vthi, vtlo, out, nullptr, nullptr,
        2048, 2048, 2048, 1024, 2048LL * 2048, 1024LL * 2048, 2048LL * 1024);
}

// round 6
// speedup vs baseline: 3.1103x; 1.1214x over previous
#include <cuda_runtime.h>
#include <cuda_bf16.h>
#include <cstdint>

// ---------------------------------------------------------------------------
// Self-attention, sm_103 baseline ISA: mma.sync m16n8k16 bf16, 3xbf16
// error compensation (Ahi*Bhi + Ahi*Blo + Alo*Bhi) on every GEMM.
// Round 6: single barrier per K-chunk + cp.async prefetch interleaved
// between MMA phases (loads fly during compute, wait residual ~0).
// ---------------------------------------------------------------------------

#define BMT 128
#define BNT 128
#define BKT 32
#define PADS 40            // padded smem row stride (bf16 elems) -> 80 bytes
#define TILE_B (128 * PADS * 2)   // 10240 bytes per bf16 tile
#define STAGE_B (4 * TILE_B)      // Ahi, Alo, Bhi, Blo
#define SMEM_SZ (2 * STAGE_B)     // 81920 bytes

static constexpr long long QKV_ONE = 16384LL * 1024LL;

__device__ __nv_bfloat16 g_xhi[16384LL * 1024], g_xlo[16384LL * 1024];
__device__ __nv_bfloat16 g_wthi[3LL * 1024 * 1024], g_wtlo[3LL * 1024 * 1024];
__device__ __nv_bfloat16 g_qkhi[2 * 16384LL * 1024], g_qklo[2 * 16384LL * 1024];
__device__ float         g_vf32[16384LL * 1024];
__device__ __nv_bfloat16 g_vthi[8LL * 1024 * 2048], g_vtlo[8LL * 1024 * 2048];
__device__ float         g_scores[8LL * 2048 * 2048];
__device__ __nv_bfloat16 g_shi[8LL * 2048 * 2048], g_slo[8LL * 2048 * 2048];

// ---------------- PTX helpers ----------------
__device__ __forceinline__ uint32_t s2u(const void* p) {
    uint32_t a;
    asm("{ .reg .u64 t; cvta.to.shared.u64 t, %1; cvt.u32.u64 %0, t; }" : "=r"(a) : "l"(p));
    return a;
}
__device__ __forceinline__ void cpasync16(uint32_t d, const void* s) {
    asm volatile("cp.async.cg.shared.global [%0], [%1], 16;" :: "r"(d), "l"(s) : "memory");
}
#define CP_COMMIT() asm volatile("cp.async.commit_group;" ::: "memory")
#define CP_WAIT(n)  asm volatile("cp.async.wait_group %0;" :: "n"(n) : "memory")

__device__ __forceinline__ void ldsm4(uint32_t* r, uint32_t a) {
    asm volatile("ldmatrix.sync.aligned.m8n8.x4.shared.b16 {%0,%1,%2,%3}, [%4];"
                 : "=r"(r[0]), "=r"(r[1]), "=r"(r[2]), "=r"(r[3]) : "r"(a));
}
__device__ __forceinline__ void mma_bf16(float* d, const uint32_t* a, const uint32_t* b) {
    asm volatile(
        "mma.sync.aligned.m16n8k16.row.col.f32.bf16.bf16.f32 "
        "{%0,%1,%2,%3}, {%4,%5,%6,%7}, {%8,%9}, {%0,%1,%2,%3};"
        : "+f"(d[0]), "+f"(d[1]), "+f"(d[2]), "+f"(d[3])
        : "r"(a[0]), "r"(a[1]), "r"(a[2]), "r"(a[3]), "r"(b[0]), "r"(b[1]));
}

// ---------------- 3xbf16 GEMM ----------------
template <bool SPLIT>
__global__ __launch_bounds__(256, 2) void bf3_gemm(
    const __nv_bfloat16* __restrict__ Ahi, const __nv_bfloat16* __restrict__ Alo,
    const __nv_bfloat16* __restrict__ Bhi, const __nv_bfloat16* __restrict__ Blo,
    float* __restrict__ C, __nv_bfloat16* __restrict__ Chi, __nv_bfloat16* __restrict__ Clo,
    int K, int lda, int ldb, int ldc,
    long long batA, long long batB, long long batC)
{
    extern __shared__ char smem[];
    const uint32_t sb = s2u(smem);
    const int tid = threadIdx.x;
    const int lane = tid & 31, warp = tid >> 5;
    const int wM = warp & 1;        // 2 warps along M (64 rows)
    const int wN = warp >> 1;       // 4 warps along N (32 cols)
    const int lm = lane >> 3, lr = lane & 7;
    const int gid = lane >> 2, tig = lane & 3;

    const long long rowBase = (long long)blockIdx.y * BMT;
    const long long colBase = (long long)blockIdx.x * BNT;
    const __nv_bfloat16* Ah = Ahi + blockIdx.z * batA;
    const __nv_bfloat16* Al = Alo + blockIdx.z * batA;
    const __nv_bfloat16* Bh = Bhi + blockIdx.z * batB;
    const __nv_bfloat16* Bl = Blo + blockIdx.z * batB;

    const uint32_t aOff = (uint32_t)(lr + (lm & 1) * 8) * (PADS * 2) + ((lm >> 1) * 8) * 2;
    const uint32_t bOff = (uint32_t)(lr + (lm >> 1) * 8) * (PADS * 2) + ((lm & 1) * 8) * 2;

    // per-thread cp.async coordinates
    const int ldr = tid >> 2;           // load row 0..63
    const int ldc4 = (tid & 3) * 16;    // byte offset along k (4 x 16B = 64B = 32 bf16)

    float acc[4][4][4];
#pragma unroll
    for (int i = 0; i < 4; i++)
#pragma unroll
        for (int j = 0; j < 4; j++)
#pragma unroll
            for (int c = 0; c < 4; c++) acc[i][j][c] = 0.f;

    const int nCh = K / BKT;

    // issue the A-half (Ahi+Alo rows) of a stage prefetch
    auto loadA = [&](int c) {
        const uint32_t st = sb + (uint32_t)(c & 1) * STAGE_B;
        const long long k0 = (long long)c * BKT;
#pragma unroll
        for (int h = 0; h < 2; h++) {
            const __nv_bfloat16* ga = h ? Al : Ah;
            const uint32_t ta = st + h * TILE_B;
#pragma unroll
            for (int i = 0; i < 2; i++) {
                int rr = ldr + i * 64;
                cpasync16(ta + rr * (PADS * 2) + ldc4,
                          (const char*)(ga + (rowBase + rr) * (long long)lda + k0) + ldc4);
            }
        }
    };
    auto loadB = [&](int c) {
        const uint32_t st = sb + (uint32_t)(c & 1) * STAGE_B;
        const long long k0 = (long long)c * BKT;
#pragma unroll
        for (int h = 0; h < 2; h++) {
            const __nv_bfloat16* gb = h ? Bl : Bh;
            const uint32_t tb = st + (2 + h) * TILE_B;
#pragma unroll
            for (int i = 0; i < 2; i++) {
                int rr = ldr + i * 64;
                cpasync16(tb + rr * (PADS * 2) + ldc4,
                          (const char*)(gb + (colBase + rr) * (long long)ldb + k0) + ldc4);
            }
        }
    };

    loadA(0); loadB(0); CP_COMMIT();

    for (int c = 0; c < nCh; ++c) {
        CP_WAIT(0);
        __syncthreads();   // single barrier per chunk: data visible + safe to overwrite buf (c+1)&1

        const uint32_t st = sb + (uint32_t)(c & 1) * STAGE_B;
        const uint32_t sAh = st, sAl = st + TILE_B, sBh = st + 2 * TILE_B, sBl = st + 3 * TILE_B;
        const bool pf = (c + 1 < nCh);

#pragma unroll
        for (int ks = 0; ks < BKT; ks += 16) {
            uint32_t af[4][4], bh_[2][4], bl_[2][4];
            const uint32_t ak = aOff + ks * 2, bk = bOff + ks * 2;

#pragma unroll
            for (int mt = 0; mt < 4; mt++)
                ldsm4(af[mt], sAh + (wM * 64 + mt * 16) * (PADS * 2) + ak);
#pragma unroll
            for (int p = 0; p < 2; p++) {
                ldsm4(bh_[p], sBh + (wN * 32 + p * 16) * (PADS * 2) + bk);
                ldsm4(bl_[p], sBl + (wN * 32 + p * 16) * (PADS * 2) + bk);
            }

            // phase 1: Ahi * Bhi
#pragma unroll
            for (int mt = 0; mt < 4; mt++)
#pragma unroll
                for (int nt = 0; nt < 4; nt++)
                    mma_bf16(acc[mt][nt], af[mt], &bh_[nt >> 1][(nt & 1) * 2]);

            if (ks == 0 && pf) loadA(c + 1);   // prefetch hides under MMAs

            // phase 2: Ahi * Blo
#pragma unroll
            for (int mt = 0; mt < 4; mt++)
#pragma unroll
                for (int nt = 0; nt < 4; nt++)
                    mma_bf16(acc[mt][nt], af[mt], &bl_[nt >> 1][(nt & 1) * 2]);

            if (ks == 0 && pf) loadB(c + 1);

            // phase 3: Alo * Bhi (reload A only)
#pragma unroll
            for (int mt = 0; mt < 4; mt++)
                ldsm4(af[mt], sAl + (wM * 64 + mt * 16) * (PADS * 2) + ak);
#pragma unroll
            for (int mt = 0; mt < 4; mt++)
#pragma unroll
                for (int nt = 0; nt < 4; nt++)
                    mma_bf16(acc[mt][nt], af[mt], &bh_[nt >> 1][(nt & 1) * 2]);
        }
        if (pf) CP_COMMIT();
    }

    // ---- epilogue ----
#pragma unroll
    for (int mt = 0; mt < 4; mt++) {
        const long long r0 = rowBase + wM * 64 + mt * 16 + gid;
#pragma unroll
        for (int nt = 0; nt < 4; nt++) {
            const long long c0 = colBase + wN * 32 + nt * 8 + tig * 2;
            if (SPLIT) {
                __nv_bfloat16* ch = Chi + blockIdx.z * batC;
                __nv_bfloat16* cl = Clo + blockIdx.z * batC;
#pragma unroll
                for (int half = 0; half < 2; half++) {
                    float v0 = acc[mt][nt][2 * half], v1 = acc[mt][nt][2 * half + 1];
                    __nv_bfloat16 h0 = __float2bfloat16(v0);
                    __nv_bfloat16 h1 = __float2bfloat16(v1);
                    __nv_bfloat16 l0 = __float2bfloat16(v0 - __bfloat162float(h0));
                    __nv_bfloat16 l1 = __float2bfloat16(v1 - __bfloat162float(h1));
                    long long idx = (r0 + half * 8) * ldc + c0;
                    *(__nv_bfloat162*)&ch[idx] = __nv_bfloat162(h0, h1);
                    *(__nv_bfloat162*)&cl[idx] = __nv_bfloat162(l0, l1);
                }
            } else {
                float* cp = C + blockIdx.z * batC;
                *(float2*)&cp[r0 * ldc + c0] =
                    make_float2(acc[mt][nt][0], acc[mt][nt][1]);
                *(float2*)&cp[(r0 + 8) * ldc + c0] =
                    make_float2(acc[mt][nt][2], acc[mt][nt][3]);
            }
        }
    }
}

// ---------------- conversion kernels ----------------
__global__ __launch_bounds__(256) void split_x(
    const float4* __restrict__ in, __nv_bfloat16* __restrict__ hi,
    __nv_bfloat16* __restrict__ lo, int n4)
{
    int i = blockIdx.x * 256 + threadIdx.x;
    if (i >= n4) return;
    float4 v = in[i];
    float vv[4] = {v.x, v.y, v.z, v.w};
    __nv_bfloat16 h[4], l[4];
#pragma unroll
    for (int j = 0; j < 4; j++) {
        h[j] = __float2bfloat16(vv[j]);
        l[j] = __float2bfloat16(vv[j] - __bfloat162float(h[j]));
    }
    ((__nv_bfloat162*)hi)[2 * i]     = __nv_bfloat162(h[0], h[1]);
    ((__nv_bfloat162*)hi)[2 * i + 1] = __nv_bfloat162(h[2], h[3]);
    ((__nv_bfloat162*)lo)[2 * i]     = __nv_bfloat162(l[0], l[1]);
    ((__nv_bfloat162*)lo)[2 * i + 1] = __nv_bfloat162(l[2], l[3]);
}

__global__ __launch_bounds__(256) void transpose_split(
    const float* __restrict__ in, __nv_bfloat16* __restrict__ hi,
    __nv_bfloat16* __restrict__ lo, int R, int C, long long batIn, long long batOut)
{
    __shared__ float t[32][33];
    const float* ip = in + blockIdx.z * batIn;
    const long long ob = blockIdx.z * batOut;
    const int c0 = blockIdx.x * 32, r0 = blockIdx.y * 32;
    const int tx = threadIdx.x, ty = threadIdx.y;
#pragma unroll
    for (int i = 0; i < 32; i += 8)
        t[ty + i][tx] = ip[(long long)(r0 + ty + i) * C + c0 + tx];
    __syncthreads();
#pragma unroll
    for (int i = 0; i < 32; i += 8) {
        float v = t[tx][ty + i];
        __nv_bfloat16 h = __float2bfloat16(v);
        __nv_bfloat16 l = __float2bfloat16(v - __bfloat162float(h));
        long long idx = ob + (long long)(c0 + ty + i) * R + r0 + tx;
        hi[idx] = h;
        lo[idx] = l;
    }
}

__global__ __launch_bounds__(256) void softmax_split(
    const float* __restrict__ sc, __nv_bfloat16* __restrict__ hi,
    __nv_bfloat16* __restrict__ lo)
{
    const float SC = 0.125f;
    const long long row = blockIdx.x;
    const float* p = sc + row * 2048;
    const int t = threadIdx.x, lane = t & 31, w = t >> 5;

    float4 v0 = ((const float4*)p)[t];
    float4 v1 = ((const float4*)p)[t + 256];
    float x[8] = {v0.x, v0.y, v0.z, v0.w, v1.x, v1.y, v1.z, v1.w};

    float m = -1e30f;
#pragma unroll
    for (int i = 0; i < 8; i++) { x[i] *= SC; m = fmaxf(m, x[i]); }
#pragma unroll
    for (int o = 16; o > 0; o >>= 1) m = fmaxf(m, __shfl_xor_sync(0xffffffffu, m, o));

    __shared__ float red[8];
    if (lane == 0) red[w] = m;
    __syncthreads();
    float bm = red[0];
#pragma unroll
    for (int i = 1; i < 8; i++) bm = fmaxf(bm, red[i]);

    float s = 0.f;
#pragma unroll
    for (int i = 0; i < 8; i++) { x[i] = expf(x[i] - bm); s += x[i]; }
#pragma unroll
    for (int o = 16; o > 0; o >>= 1) s += __shfl_xor_sync(0xffffffffu, s, o);
    __syncthreads();
    if (lane == 0) red[w] = s;
    __syncthreads();
    float tot = 0.f;
#pragma unroll
    for (int i = 0; i < 8; i++) tot += red[i];
    const float inv = 1.0f / tot;

    __nv_bfloat162* hp0 = (__nv_bfloat162*)(hi + row * 2048) + 2 * t;
    __nv_bfloat162* lp0 = (__nv_bfloat162*)(lo + row * 2048) + 2 * t;
    __nv_bfloat162* hp1 = hp0 + 512;
    __nv_bfloat162* lp1 = lp0 + 512;
    __nv_bfloat16 h[8], l[8];
#pragma unroll
    for (int i = 0; i < 8; i++) {
        float y = x[i] * inv;
        h[i] = __float2bfloat16(y);
        l[i] = __float2bfloat16(y - __bfloat162float(h[i]));
    }
    hp0[0] = __nv_bfloat162(h[0], h[1]); hp0[1] = __nv_bfloat162(h[2], h[3]);
    hp1[0] = __nv_bfloat162(h[4], h[5]); hp1[1] = __nv_bfloat162(h[6], h[7]);
    lp0[0] = __nv_bfloat162(l[0], l[1]); lp0[1] = __nv_bfloat162(l[2], l[3]);
    lp1[0] = __nv_bfloat162(l[4], l[5]); lp1[1] = __nv_bfloat162(l[6], l[7]);
}

// ---------------- host ----------------
extern "C" void kernel_launch(void* const* d_in, const int* in_sizes, int n_in,
                              void* d_out, int out_size) {
    const float* x = (const float*)d_in[0];
    const float* w = (const float*)d_in[1];
    float* out = (float*)d_out;

    __nv_bfloat16 *xhi, *xlo, *wthi, *wtlo, *qkhi, *qklo, *vthi, *vtlo, *shi, *slo;
    float *vf32, *scores;
    cudaGetSymbolAddress((void**)&xhi, g_xhi);
    cudaGetSymbolAddress((void**)&xlo, g_xlo);
    cudaGetSymbolAddress((void**)&wthi, g_wthi);
    cudaGetSymbolAddress((void**)&wtlo, g_wtlo);
    cudaGetSymbolAddress((void**)&qkhi, g_qkhi);
    cudaGetSymbolAddress((void**)&qklo, g_qklo);
    cudaGetSymbolAddress((void**)&vf32, g_vf32);
    cudaGetSymbolAddress((void**)&vthi, g_vthi);
    cudaGetSymbolAddress((void**)&vtlo, g_vtlo);
    cudaGetSymbolAddress((void**)&scores, g_scores);
    cudaGetSymbolAddress((void**)&shi, g_shi);
    cudaGetSymbolAddress((void**)&slo, g_slo);

    cudaFuncSetAttribute(bf3_gemm<true>,  cudaFuncAttributeMaxDynamicSharedMemorySize, SMEM_SZ);
    cudaFuncSetAttribute(bf3_gemm<false>, cudaFuncAttributeMaxDynamicSharedMemorySize, SMEM_SZ);

    split_x<<<16384, 256>>>((const float4*)x, xhi, xlo, 16384 * 1024 / 4);

    transpose_split<<<dim3(32, 32, 3), dim3(32, 8)>>>(
        w, wthi, wtlo, 1024, 1024, 1024LL * 1024, 1024LL * 1024);

    bf3_gemm<true><<<dim3(8, 128, 2), 256, SMEM_SZ>>>(
        xhi, xlo, wthi, wtlo, nullptr, qkhi, qklo,
        1024, 1024, 1024, 1024, 0LL, 1024LL * 1024, QKV_ONE);

    bf3_gemm<false><<<dim3(8, 128, 1), 256, SMEM_SZ>>>(
        xhi, xlo, wthi + 2LL * 1024 * 1024, wtlo + 2LL * 1024 * 1024,
        vf32, nullptr, nullptr,
        1024, 1024, 1024, 1024, 0LL, 0LL, 0LL);

    transpose_split<<<dim3(32, 64, 8), dim3(32, 8)>>>(
        vf32, vthi, vtlo, 2048, 1024, 2048LL * 1024, 1024LL * 2048);

    bf3_gemm<false><<<dim3(16, 16, 8), 256, SMEM_SZ>>>(
        qkhi, qklo, qkhi + QKV_ONE, qklo + QKV_ONE, scores, nullptr, nullptr,
        1024, 1024, 1024, 2048, 2048LL * 1024, 2048LL * 1024, 2048LL * 2048);

    softmax_split<<<16384, 256>>>(scores, shi, slo);

    bf3_gemm<false><<<dim3(8, 16, 8), 256, SMEM_SZ>>>(
        shi, slo, vthi, vtlo, out, nullptr, nullptr,
        2048, 2048, 2048, 1024, 2048LL * 2048, 1024LL * 2048, 2048LL * 1024);
}

// round 7
// speedup vs baseline: 6.1224x; 1.9685x over previous
#include <cuda_runtime.h>
#include <cuda_fp16.h>
#include <cstdint>

// ---------------------------------------------------------------------------
// Self-attention, sm_103 baseline ISA. Round 7: single-product fp16
// mma.sync m16n8k16 on every GEMM (fp32 accumulate; only error source is
// fp16 operand quantization ~1.4e-4 RMS). 3x less MMA work than 3xbf16.
// V projection is produced directly transposed (no transpose kernel).
// BKT=64, 2-stage cp.async, single barrier per chunk, 2 CTAs/SM.
// ---------------------------------------------------------------------------

#define BMT 128
#define BNT 128
#define BKT 64
#define SSTR 144                  // smem row stride bytes (128B data + 16 pad)
#define TILE_B (128 * SSTR)       // 18432 B per tile
#define STAGE_B (2 * TILE_B)      // A + B
#define SMEM_SZ (2 * STAGE_B)     // 73728 B (double buffered)

static constexpr long long QKV_ONE = 16384LL * 1024LL;

__device__ __half g_xh[16384LL * 1024];
__device__ __half g_wt[3LL * 1024 * 1024];
__device__ __half g_qkh[2 * 16384LL * 1024];
__device__ __half g_vt[8LL * 1024 * 2048];
__device__ float  g_scores[8LL * 2048 * 2048];
__device__ __half g_ah[8LL * 2048 * 2048];

// ---------------- PTX helpers ----------------
__device__ __forceinline__ uint32_t s2u(const void* p) {
    uint32_t a;
    asm("{ .reg .u64 t; cvta.to.shared.u64 t, %1; cvt.u32.u64 %0, t; }" : "=r"(a) : "l"(p));
    return a;
}
__device__ __forceinline__ void cpasync16(uint32_t d, const void* s) {
    asm volatile("cp.async.cg.shared.global [%0], [%1], 16;" :: "r"(d), "l"(s) : "memory");
}
#define CP_COMMIT() asm volatile("cp.async.commit_group;" ::: "memory")
#define CP_WAIT(n)  asm volatile("cp.async.wait_group %0;" :: "n"(n) : "memory")

__device__ __forceinline__ void ldsm4(uint32_t* r, uint32_t a) {
    asm volatile("ldmatrix.sync.aligned.m8n8.x4.shared.b16 {%0,%1,%2,%3}, [%4];"
                 : "=r"(r[0]), "=r"(r[1]), "=r"(r[2]), "=r"(r[3]) : "r"(a));
}
__device__ __forceinline__ void mma_f16(float* d, const uint32_t* a, const uint32_t* b) {
    asm volatile(
        "mma.sync.aligned.m16n8k16.row.col.f32.f16.f16.f32 "
        "{%0,%1,%2,%3}, {%4,%5,%6,%7}, {%8,%9}, {%0,%1,%2,%3};"
        : "+f"(d[0]), "+f"(d[1]), "+f"(d[2]), "+f"(d[3])
        : "r"(a[0]), "r"(a[1]), "r"(a[2]), "r"(a[3]), "r"(b[0]), "r"(b[1]));
}

// ---------------- fp16 GEMM: C[M,N] = sum_k A[m][k]*B[n][k] ----------------
// OUT == 0: fp32 C.  OUT == 1: fp16 C.
template <int OUT>
__global__ __launch_bounds__(256, 2) void h_gemm(
    const __half* __restrict__ Ag, const __half* __restrict__ Bg,
    float* __restrict__ Cf, __half* __restrict__ Ch,
    int K, int lda, int ldb, int ldc,
    long long batA, long long batB, long long batC)
{
    extern __shared__ char smem[];
    const uint32_t sb = s2u(smem);
    const int tid = threadIdx.x;
    const int lane = tid & 31, warp = tid >> 5;
    const int wM = warp & 1;        // 2 warps along M (64 rows)
    const int wN = warp >> 1;       // 4 warps along N (32 cols)
    const int lm = lane >> 3, lr = lane & 7;
    const int gid = lane >> 2, tig = lane & 3;

    const long long rowBase = (long long)blockIdx.y * BMT;
    const long long colBase = (long long)blockIdx.x * BNT;
    const char* A = (const char*)(Ag + blockIdx.z * batA);
    const char* B = (const char*)(Bg + blockIdx.z * batB);

    const uint32_t aOff = (uint32_t)(lr + (lm & 1) * 8) * SSTR + ((lm >> 1) * 8) * 2;
    const uint32_t bOff = (uint32_t)(lr + (lm >> 1) * 8) * SSTR + ((lm & 1) * 8) * 2;

    // per-thread cp.async coordinates: 2 threads per 128B row
    const int ldr = tid >> 1;            // row 0..127
    const int ldcb = (tid & 1) * 64;     // byte offset within row (0 or 64)

    float acc[4][4][4];
#pragma unroll
    for (int i = 0; i < 4; i++)
#pragma unroll
        for (int j = 0; j < 4; j++)
#pragma unroll
            for (int c = 0; c < 4; c++) acc[i][j][c] = 0.f;

    const int nCh = K / BKT;

    auto loadA = [&](int c) {
        const uint32_t st = sb + (uint32_t)(c & 1) * STAGE_B;
        const long long gb = (rowBase + ldr) * (long long)lda * 2 + (long long)c * (BKT * 2);
#pragma unroll
        for (int i = 0; i < 4; i++)
            cpasync16(st + ldr * SSTR + ldcb + i * 16, A + gb + ldcb + i * 16);
    };
    auto loadB = [&](int c) {
        const uint32_t st = sb + (uint32_t)(c & 1) * STAGE_B + TILE_B;
        const long long gb = (colBase + ldr) * (long long)ldb * 2 + (long long)c * (BKT * 2);
#pragma unroll
        for (int i = 0; i < 4; i++)
            cpasync16(st + ldr * SSTR + ldcb + i * 16, B + gb + ldcb + i * 16);
    };

    loadA(0); loadB(0); CP_COMMIT();

    for (int c = 0; c < nCh; ++c) {
        CP_WAIT(0);
        __syncthreads();   // data visible + safe to overwrite buf (c+1)&1

        const uint32_t sA = sb + (uint32_t)(c & 1) * STAGE_B;
        const uint32_t sB = sA + TILE_B;
        const bool pf = (c + 1 < nCh);

#pragma unroll
        for (int ks = 0; ks < BKT; ks += 16) {
            uint32_t af[4][4], bf_[2][4];
            const uint32_t ak = aOff + ks * 2, bk = bOff + ks * 2;
#pragma unroll
            for (int mt = 0; mt < 4; mt++)
                ldsm4(af[mt], sA + (wM * 64 + mt * 16) * SSTR + ak);
#pragma unroll
            for (int p = 0; p < 2; p++)
                ldsm4(bf_[p], sB + (wN * 32 + p * 16) * SSTR + bk);

#pragma unroll
            for (int mt = 0; mt < 4; mt++)
#pragma unroll
                for (int nt = 0; nt < 4; nt++)
                    mma_f16(acc[mt][nt], af[mt], &bf_[nt >> 1][(nt & 1) * 2]);

            if (ks == 0 && pf) loadA(c + 1);       // prefetch hides under MMAs
            if (ks == 16 && pf) { loadB(c + 1); CP_COMMIT(); }
        }
    }

    // ---- epilogue ----
#pragma unroll
    for (int mt = 0; mt < 4; mt++) {
        const long long r0 = rowBase + wM * 64 + mt * 16 + gid;
#pragma unroll
        for (int nt = 0; nt < 4; nt++) {
            const long long c0 = colBase + wN * 32 + nt * 8 + tig * 2;
            if (OUT == 1) {
                __half* cp = Ch + blockIdx.z * batC;
                *(__half2*)&cp[r0 * ldc + c0] =
                    __floats2half2_rn(acc[mt][nt][0], acc[mt][nt][1]);
                *(__half2*)&cp[(r0 + 8) * ldc + c0] =
                    __floats2half2_rn(acc[mt][nt][2], acc[mt][nt][3]);
            } else {
                float* cp = Cf + blockIdx.z * batC;
                *(float2*)&cp[r0 * ldc + c0] =
                    make_float2(acc[mt][nt][0], acc[mt][nt][1]);
                *(float2*)&cp[(r0 + 8) * ldc + c0] =
                    make_float2(acc[mt][nt][2], acc[mt][nt][3]);
            }
        }
    }
}

// ---------------- conversion kernels ----------------
__global__ __launch_bounds__(256) void cvt_x(
    const float4* __restrict__ in, __half* __restrict__ out, int n4)
{
    int i = blockIdx.x * 256 + threadIdx.x;
    if (i >= n4) return;
    float4 v = in[i];
    ((__half2*)out)[2 * i]     = __floats2half2_rn(v.x, v.y);
    ((__half2*)out)[2 * i + 1] = __floats2half2_rn(v.z, v.w);
}

// out[z][c][r] = in[z][r][c] as fp16
__global__ __launch_bounds__(256) void transpose_cvt(
    const float* __restrict__ in, __half* __restrict__ out,
    int R, int C, long long batIn, long long batOut)
{
    __shared__ float t[32][33];
    const float* ip = in + blockIdx.z * batIn;
    const long long ob = blockIdx.z * batOut;
    const int c0 = blockIdx.x * 32, r0 = blockIdx.y * 32;
    const int tx = threadIdx.x, ty = threadIdx.y;
#pragma unroll
    for (int i = 0; i < 32; i += 8)
        t[ty + i][tx] = ip[(long long)(r0 + ty + i) * C + c0 + tx];
    __syncthreads();
#pragma unroll
    for (int i = 0; i < 32; i += 8)
        out[ob + (long long)(c0 + ty + i) * R + r0 + tx] = __float2half(t[tx][ty + i]);
}

// softmax over rows of 2048; 1/8 scale folded in; fp16 output
__global__ __launch_bounds__(256) void softmax_h(
    const float* __restrict__ sc, __half* __restrict__ out)
{
    const float SC = 0.125f;
    const long long row = blockIdx.x;
    const float* p = sc + row * 2048;
    const int t = threadIdx.x, lane = t & 31, w = t >> 5;

    float4 v0 = ((const float4*)p)[t];
    float4 v1 = ((const float4*)p)[t + 256];
    float x[8] = {v0.x, v0.y, v0.z, v0.w, v1.x, v1.y, v1.z, v1.w};

    float m = -1e30f;
#pragma unroll
    for (int i = 0; i < 8; i++) { x[i] *= SC; m = fmaxf(m, x[i]); }
#pragma unroll
    for (int o = 16; o > 0; o >>= 1) m = fmaxf(m, __shfl_xor_sync(0xffffffffu, m, o));

    __shared__ float red[8];
    if (lane == 0) red[w] = m;
    __syncthreads();
    float bm = red[0];
#pragma unroll
    for (int i = 1; i < 8; i++) bm = fmaxf(bm, red[i]);

    float s = 0.f;
#pragma unroll
    for (int i = 0; i < 8; i++) { x[i] = expf(x[i] - bm); s += x[i]; }
#pragma unroll
    for (int o = 16; o > 0; o >>= 1) s += __shfl_xor_sync(0xffffffffu, s, o);
    __syncthreads();
    if (lane == 0) red[w] = s;
    __syncthreads();
    float tot = 0.f;
#pragma unroll
    for (int i = 0; i < 8; i++) tot += red[i];
    const float inv = 1.0f / tot;

    __half2* op = (__half2*)(out + row * 2048);
    op[2 * t]           = __floats2half2_rn(x[0] * inv, x[1] * inv);
    op[2 * t + 1]       = __floats2half2_rn(x[2] * inv, x[3] * inv);
    op[2 * t + 512]     = __floats2half2_rn(x[4] * inv, x[5] * inv);
    op[2 * t + 513]     = __floats2half2_rn(x[6] * inv, x[7] * inv);
}

// ---------------- host ----------------
extern "C" void kernel_launch(void* const* d_in, const int* in_sizes, int n_in,
                              void* d_out, int out_size) {
    const float* x = (const float*)d_in[0];
    const float* w = (const float*)d_in[1];
    float* out = (float*)d_out;

    __half *xh, *wt, *qkh, *vt, *ah;
    float* scores;
    cudaGetSymbolAddress((void**)&xh, g_xh);
    cudaGetSymbolAddress((void**)&wt, g_wt);
    cudaGetSymbolAddress((void**)&qkh, g_qkh);
    cudaGetSymbolAddress((void**)&vt, g_vt);
    cudaGetSymbolAddress((void**)&scores, g_scores);
    cudaGetSymbolAddress((void**)&ah, g_ah);

    cudaFuncSetAttribute(h_gemm<0>, cudaFuncAttributeMaxDynamicSharedMemorySize, SMEM_SZ);
    cudaFuncSetAttribute(h_gemm<1>, cudaFuncAttributeMaxDynamicSharedMemorySize, SMEM_SZ);

    // 1) x -> fp16
    cvt_x<<<16384, 256>>>((const float4*)x, xh, 16384 * 1024 / 4);

    // 2) W transpose -> wt[z][d][h] fp16
    transpose_cvt<<<dim3(32, 32, 3), dim3(32, 8)>>>(
        w, wt, 1024, 1024, 1024LL * 1024, 1024LL * 1024);

    // 3) Q,K projections: [s][d] fp16  (M=16384, N=1024, K=1024; z = Q/K)
    h_gemm<1><<<dim3(8, 128, 2), 256, SMEM_SZ>>>(
        xh, wt, nullptr, qkh,
        1024, 1024, 1024, 1024, 0LL, 1024LL * 1024, QKV_ONE);

    // 4) V projection, produced TRANSPOSED: vt[b][d][s] fp16
    //    C[d][s] = sum_h Wv_t[d][h] * x_b[s][h]   (M=1024, N=2048, K=1024)
    h_gemm<1><<<dim3(16, 8, 8), 256, SMEM_SZ>>>(
        wt + 2LL * 1024 * 1024, xh, nullptr, vt,
        1024, 1024, 1024, 2048, 0LL, 2048LL * 1024, 1024LL * 2048);

    // 5) S = Q @ K^T per batch -> fp32 (M=2048, N=2048, K=1024)
    h_gemm<0><<<dim3(16, 16, 8), 256, SMEM_SZ>>>(
        qkh, qkh + QKV_ONE, scores, nullptr,
        1024, 1024, 1024, 2048, 2048LL * 1024, 2048LL * 1024, 2048LL * 2048);

    // 6) softmax -> fp16 A
    softmax_h<<<16384, 256>>>(scores, ah);

    // 7) out = A @ V per batch (M=2048, N=1024, K=2048); B = vt[d][s] K-major
    h_gemm<0><<<dim3(8, 16, 8), 256, SMEM_SZ>>>(
        ah, vt, out, nullptr,
        2048, 2048, 2048, 1024, 2048LL * 2048, 1024LL * 2048, 2048LL * 1024);
}